// round 3
// baseline (speedup 1.0000x reference)
#include <cuda_runtime.h>
#include <math_constants.h>

// Problem constants
#define BATCH 16384
#define NN    50
#define HH    128
#define NPAD  52   // padded neighbor stride in smem (even for 8/16B alignment)

typedef unsigned long long ull;

// ---------------------------------------------------------------------------
// Static device scratch (no allocations allowed)
// ---------------------------------------------------------------------------
__device__ float g_WT_user[128 * 128];   // W^T: [d][h]
__device__ float g_WT_news[128 * 128];
__device__ float g_WT_sem [384 * 128];
__device__ unsigned char g_mask_user[BATCH * NN];
__device__ unsigned char g_mask_news[BATCH * NN];
__device__ int g_mask_mode;  // 0=uint8, 1=int32, 2=float32

// ---------------------------------------------------------------------------
// Mask dtype sniffing: scan first 64KB (in-bounds for every candidate dtype:
// smallest buffer is 819200 bytes as uint8). Words are exactly {0,1} for i32,
// {0,0x3F800000} for f32, and mixed packed bytes for uint8-bool.
// ---------------------------------------------------------------------------
__global__ void detect_mask_kernel(const unsigned int* __restrict__ w) {
    __shared__ int fF, fU;
    if (threadIdx.x == 0) { fF = 0; fU = 0; }
    __syncthreads();
    int lf = 0, lu = 0;
    for (int i = threadIdx.x; i < 16384; i += 256) {
        unsigned v = w[i];
        if (v == 0x3F800000u) lf = 1;
        else if (v != 0u && v != 1u) lu = 1;
    }
    if (lf) atomicOr(&fF, 1);
    if (lu) atomicOr(&fU, 1);
    __syncthreads();
    if (threadIdx.x == 0) g_mask_mode = fF ? 2 : (fU ? 0 : 1);
}

__global__ void expand_mask_kernel(const void* __restrict__ src,
                                   unsigned char* __restrict__ dst, int n) {
    int i = blockIdx.x * blockDim.x + threadIdx.x;
    if (i >= n) return;
    int m = g_mask_mode;
    unsigned char v;
    if (m == 0)      v = (((const unsigned char*)src)[i] != 0);
    else if (m == 1) v = (((const int*)src)[i] != 0);
    else             v = (((const float*)src)[i] != 0.0f);
    dst[i] = v;
}

// W: [H, Din] row-major -> WT: [Din, H] so main-loop weight reads are coalesced.
__global__ void transpose_w_kernel(const float* __restrict__ W,
                                   float* __restrict__ WT, int Din) {
    int i = blockIdx.x * blockDim.x + threadIdx.x;
    if (i >= Din * HH) return;
    int d = i >> 7;
    int h = i & 127;
    WT[i] = W[h * Din + d];
}

// ---------------------------------------------------------------------------
// Packed fp32x2 helpers (sm_103a)
// ---------------------------------------------------------------------------
__device__ __forceinline__ ull packf2(float x, float y) {
    ull r;
    asm("mov.b64 %0, {%1, %2};" : "=l"(r) : "f"(x), "f"(y));
    return r;
}
__device__ __forceinline__ void unpackf2(ull v, float& x, float& y) {
    asm("mov.b64 {%0, %1}, %2;" : "=f"(x), "=f"(y) : "l"(v));
}
__device__ __forceinline__ void ffma2(ull& d, ull a, ull b) {
    asm("fma.rn.f32x2 %0, %1, %2, %0;" : "+l"(d) : "l"(a), "l"(b));
}

// ---------------------------------------------------------------------------
// Fused aggregation kernel: one CTA (128 threads) per batch row.
//   thread h owns output channel h; holds z[n,h] for all 50 n in 25 packed
//   fp32x2 accumulators. x tile lives transposed in smem so the inner loop is
//   ld.shared.v2.b64 (16B, broadcast) + fma.rn.f32x2.
// ---------------------------------------------------------------------------
template <int D>
__global__ void __launch_bounds__(128)
agg_kernel(const float* __restrict__ x,
           const unsigned char* __restrict__ mask,
           const float* __restrict__ WT,
           const float* __restrict__ bias,
           const float* __restrict__ uvec,
           const float* __restrict__ qvec,
           float* __restrict__ out) {
    extern __shared__ float xT[];          // [D][NPAD]
    __shared__ float s_ws[4][NN];          // per-warp partial score sums
    __shared__ float s_attn[NN];

    const int t = threadIdx.x;             // == output channel h
    const int b = blockIdx.x;
    const float* xb = x + (size_t)b * NN * D;

    // ---- load + transpose x tile into smem: xT[d][n] ----
    for (int n0 = 0; n0 < NN; n0 += 2) {
        #pragma unroll
        for (int d = t; d < D; d += 128) {
            float v0 = xb[(size_t)n0 * D + d];
            float v1 = xb[(size_t)(n0 + 1) * D + d];
            *(float2*)&xT[d * NPAD + n0] = make_float2(v0, v1);
        }
    }
    __syncthreads();

    const float bu = bias[t] + uvec[t];
    const float qh = qvec[t];

    ull acc[25];
    #pragma unroll
    for (int j = 0; j < 25; ++j) acc[j] = 0ULL;

    const unsigned xTs = (unsigned)__cvta_generic_to_shared(xT);

    // ---- z[n,h] = sum_d W[h][d] * x[n][d], packed 2 neighbors per FFMA2 ----
    for (int d = 0; d < D; ++d) {
        float w = WT[d * HH + t];          // coalesced, L2/L1-resident
        ull w2 = packf2(w, w);
        unsigned base = xTs + (unsigned)d * (NPAD * 4);
        #pragma unroll
        for (int j4 = 0; j4 < 12; ++j4) {  // neighbors 0..47 via 16B loads
            ull a, c;
            asm("ld.shared.v2.b64 {%0, %1}, [%2];"
                : "=l"(a), "=l"(c) : "r"(base + j4 * 16));
            ffma2(acc[2 * j4], w2, a);
            ffma2(acc[2 * j4 + 1], w2, c);
        }
        {                                   // neighbors 48,49
            ull a;
            asm("ld.shared.b64 %0, [%1];" : "=l"(a) : "r"(base + 192));
            ffma2(acc[24], w2, a);
        }
    }

    // ---- scores: s[n] = sum_h q[h] * tanh(z[n,h] + b[h] + u[h]) ----
    const int lane = t & 31, warp = t >> 5;
    #pragma unroll
    for (int j = 0; j < 25; ++j) {
        float z0, z1;
        unpackf2(acc[j], z0, z1);
        float c0 = qh * tanhf(z0 + bu);
        float c1 = qh * tanhf(z1 + bu);
        #pragma unroll
        for (int o = 16; o; o >>= 1) {
            c0 += __shfl_xor_sync(0xffffffffu, c0, o);
            c1 += __shfl_xor_sync(0xffffffffu, c1, o);
        }
        if (lane == 0) {
            s_ws[warp][2 * j]     = c0;
            s_ws[warp][2 * j + 1] = c1;
        }
    }
    __syncthreads();

    // ---- masked softmax over 50 neighbors (warp 0, 2 elems/lane) ----
    if (t < 32) {
        const unsigned char* mb = mask + (size_t)b * NN;
        float a0, a1 = -CUDART_INF_F;
        {
            float s = s_ws[0][t] + s_ws[1][t] + s_ws[2][t] + s_ws[3][t];
            a0 = mb[t] ? s : -CUDART_INF_F;
        }
        if (t + 32 < NN) {
            float s = s_ws[0][t + 32] + s_ws[1][t + 32] + s_ws[2][t + 32] + s_ws[3][t + 32];
            a1 = mb[t + 32] ? s : -CUDART_INF_F;
        }
        float mx = fmaxf(a0, a1);
        #pragma unroll
        for (int o = 16; o; o >>= 1)
            mx = fmaxf(mx, __shfl_xor_sync(0xffffffffu, mx, o));
        float e0 = expf(a0 - mx);                       // -inf -> 0
        float e1 = (t + 32 < NN) ? expf(a1 - mx) : 0.0f;
        float sm = e0 + e1;
        #pragma unroll
        for (int o = 16; o; o >>= 1)
            sm += __shfl_xor_sync(0xffffffffu, sm, o);
        float inv = 1.0f / sm;
        s_attn[t] = e0 * inv;
        if (t + 32 < NN) s_attn[t + 32] = e1 * inv;
    }
    __syncthreads();

    // ---- out[b][d] = sum_n attn[n] * x[n][d] ----
    for (int d = t; d < D; d += 128) {
        const float* xr = &xT[d * NPAD];
        float o = 0.0f;
        #pragma unroll
        for (int n = 0; n < NN; ++n) o = fmaf(s_attn[n], xr[n], o);
        out[(size_t)b * D + d] = o;
    }
}

// ---------------------------------------------------------------------------
// Launch: inputs (metadata order):
//  0 neighbor_users (B,N,128) f32      5 W_user  6 b_user  7 u_user  8 q_user
//  1 neighbor_news_ids (B,N,128) f32   9 W_news 10 b_news 11 u_news 12 q_news
//  2 neighbor_news_semantic (B,N,384) 13 W_sem  14 b_sem  15 u_sem  16 q_sem
//  3 neighbor_user_mask (B,N) bool
//  4 neighbor_news_mask (B,N) bool
// Output: concat [agg_users (B,128) | agg_news (B,128) | agg_sem (B,384)] f32
// ---------------------------------------------------------------------------
extern "C" void kernel_launch(void* const* d_in, const int* in_sizes, int n_in,
                              void* d_out, int out_size) {
    const float* users = (const float*)d_in[0];
    const float* news  = (const float*)d_in[1];
    const float* sem   = (const float*)d_in[2];
    const void*  mu    = d_in[3];
    const void*  mn    = d_in[4];
    const float* W_user = (const float*)d_in[5];
    const float* b_user = (const float*)d_in[6];
    const float* u_user = (const float*)d_in[7];
    const float* q_user = (const float*)d_in[8];
    const float* W_news = (const float*)d_in[9];
    const float* b_news = (const float*)d_in[10];
    const float* u_news = (const float*)d_in[11];
    const float* q_news = (const float*)d_in[12];
    const float* W_sem  = (const float*)d_in[13];
    const float* b_sem  = (const float*)d_in[14];
    const float* u_sem  = (const float*)d_in[15];
    const float* q_sem  = (const float*)d_in[16];
    float* out = (float*)d_out;

    void* p;
    cudaGetSymbolAddress(&p, g_WT_user);  float* wt_u = (float*)p;
    cudaGetSymbolAddress(&p, g_WT_news);  float* wt_n = (float*)p;
    cudaGetSymbolAddress(&p, g_WT_sem);   float* wt_s = (float*)p;
    cudaGetSymbolAddress(&p, g_mask_user); unsigned char* gmu = (unsigned char*)p;
    cudaGetSymbolAddress(&p, g_mask_news); unsigned char* gmn = (unsigned char*)p;

    // Mask dtype detection + canonicalization
    detect_mask_kernel<<<1, 256>>>((const unsigned int*)mu);
    expand_mask_kernel<<<(BATCH * NN + 255) / 256, 256>>>(mu, gmu, BATCH * NN);
    expand_mask_kernel<<<(BATCH * NN + 255) / 256, 256>>>(mn, gmn, BATCH * NN);

    // Weight transposes (tiny)
    transpose_w_kernel<<<(128 * 128 + 255) / 256, 256>>>(W_user, wt_u, 128);
    transpose_w_kernel<<<(128 * 128 + 255) / 256, 256>>>(W_news, wt_n, 128);
    transpose_w_kernel<<<(384 * 128 + 255) / 256, 256>>>(W_sem,  wt_s, 384);

    const int smem128 = 128 * NPAD * 4;   // 26624 B
    const int smem384 = 384 * NPAD * 4;   // 79872 B
    cudaFuncSetAttribute(agg_kernel<384>,
                         cudaFuncAttributeMaxDynamicSharedMemorySize, smem384);

    agg_kernel<128><<<BATCH, 128, smem128>>>(users, gmu, wt_u,
                                             b_user, u_user, q_user, out);
    agg_kernel<128><<<BATCH, 128, smem128>>>(news, gmn, wt_n,
                                             b_news, u_news, q_news,
                                             out + (size_t)BATCH * 128);
    agg_kernel<384><<<BATCH, 128, smem384>>>(sem, gmn, wt_s,
                                             b_sem, u_sem, q_sem,
                                             out + (size_t)BATCH * 256);
}

// round 9
// speedup vs baseline: 1.5370x; 1.5370x over previous
#include <cuda_runtime.h>
#include <math_constants.h>
#include <cstdint>

#define BATCH 16384
#define NN    50
#define HH    128
#define ROWS  (BATCH * NN)        // 819200 = 6400 * 128 exactly

typedef unsigned int       u32;
typedef unsigned long long u64;

// ---------------------------------------------------------------------------
// Static device scratch (no allocations allowed)
// ---------------------------------------------------------------------------
__device__ unsigned char g_mask_user[ROWS];
__device__ unsigned char g_mask_news[ROWS];
__device__ int g_mask_mode;  // 0=uint8, 1=int32, 2=float32
__device__ float g_WT_u[128 * 128];   // W^T: [d][h]
__device__ float g_WT_n[128 * 128];
__device__ float g_WT_s[384 * 128];
__device__ float g_S_u[ROWS];         // raw (pre-mask) attention scores
__device__ float g_S_n[ROWS];
__device__ float g_S_s[ROWS];

// ---------------------------------------------------------------------------
// Mask dtype sniffing (proven in round 3): scan first 64KB as u32 words.
// ---------------------------------------------------------------------------
__global__ void detect_mask_kernel(const unsigned int* __restrict__ w) {
    __shared__ int fF, fU;
    if (threadIdx.x == 0) { fF = 0; fU = 0; }
    __syncthreads();
    int lf = 0, lu = 0;
    for (int i = threadIdx.x; i < 16384; i += 256) {
        unsigned v = w[i];
        if (v == 0x3F800000u) lf = 1;
        else if (v != 0u && v != 1u) lu = 1;
    }
    if (lf) atomicOr(&fF, 1);
    if (lu) atomicOr(&fU, 1);
    __syncthreads();
    if (threadIdx.x == 0) g_mask_mode = fF ? 2 : (fU ? 0 : 1);
}

__global__ void expand_mask_kernel(const void* __restrict__ src,
                                   unsigned char* __restrict__ dst, int n) {
    int i = blockIdx.x * blockDim.x + threadIdx.x;
    if (i >= n) return;
    int m = g_mask_mode;
    unsigned char v;
    if (m == 0)      v = (((const unsigned char*)src)[i] != 0);
    else if (m == 1) v = (((const int*)src)[i] != 0);
    else             v = (((const float*)src)[i] != 0.0f);
    dst[i] = v;
}

// ---------------------------------------------------------------------------
// W: [H, Din] row-major -> WT: [Din, H] (coalesced B-tile loads in the GEMM).
// One launch handles all three weight matrices.
// ---------------------------------------------------------------------------
__global__ void prep_wt_kernel(const float* __restrict__ Wu,
                               const float* __restrict__ Wn,
                               const float* __restrict__ Ws) {
    int i = blockIdx.x * blockDim.x + threadIdx.x;
    const float* src; float* dst; int off, Din;
    if (i < 16384)      { src = Wu; dst = g_WT_u; off = i;          Din = 128; }
    else if (i < 32768) { src = Wn; dst = g_WT_n; off = i - 16384;  Din = 128; }
    else if (i < 81920) { src = Ws; dst = g_WT_s; off = i - 32768;  Din = 384; }
    else return;
    int d = off >> 7, h = off & 127;
    dst[off] = src[h * Din + d];
}

// ---------------------------------------------------------------------------
// Packed fp32x2 helpers (proven in round 3: rel_err 5.3e-7)
// ---------------------------------------------------------------------------
__device__ __forceinline__ u64 packf2(float x, float y) {
    u64 r;
    asm("mov.b64 %0, {%1, %2};" : "=l"(r) : "f"(x), "f"(y));
    return r;
}
__device__ __forceinline__ void unpackf2(u64 v, float& x, float& y) {
    asm("mov.b64 {%0, %1}, %2;" : "=f"(x), "=f"(y) : "l"(v));
}
__device__ __forceinline__ void ffma2(u64& d, u64 a, u64 b) {
    asm("fma.rn.f32x2 %0, %1, %2, %0;" : "+l"(d) : "l"(a), "l"(b));
}

// Fast tanh: 1 - 2/(exp(2x)+1). MUFU-based; abs err ~1e-7 (gate is 1e-3).
// Overflow-safe: x>>0 -> e=inf -> 1; x<<0 -> e=0 -> -1.
__device__ __forceinline__ float tanh_fast(float x) {
    float e = __expf(2.0f * x);
    return 1.0f - 2.0f / (e + 1.0f);
}

// ---------------------------------------------------------------------------
// GEMM + fused score kernel.
//   Z = X (ROWS x D) * WT (D x 128), fp32, register-tiled 128x128 CTA tile,
//   8x8 thread tile on 256 threads, fp32x2 FFMA in the inner product.
//   Epilogue computes s[row] = sum_h q[h] * tanh(z[row][h] + b[h] + u[h])
//   directly from accumulators -> z never touches memory.
// ---------------------------------------------------------------------------
template <int D>
__global__ void __launch_bounds__(256)
gemm_score_kernel(const float* __restrict__ x,
                  const float* __restrict__ WT,
                  const float* __restrict__ bias,
                  const float* __restrict__ uvec,
                  const float* __restrict__ qvec,
                  float* __restrict__ sraw) {
    __shared__ float As[16][128];       // As[k][m]  (A stored transposed)
    __shared__ float Bs[16][128];       // Bs[k][h]
    __shared__ float sq[128], sbu[128];
    __shared__ float sred[128][17];     // padded: conflict-light partial scores

    const int tid = threadIdx.x;
    const int tm = tid >> 4, tn = tid & 15;          // 16x16 thread grid
    const size_t r0 = (size_t)blockIdx.x * 128;

    if (tid < 128) { sq[tid] = qvec[tid]; sbu[tid] = bias[tid] + uvec[tid]; }

    // Loader mapping
    const int la_row = tid >> 1;                     // A: 128 rows, 2 threads/row
    const int la_kh  = (tid & 1) * 8;                //    each thread 8 of 16 k's
    const int lb_k   = tid >> 4;                     // B: 16 k-rows
    const int lb_h   = (tid & 15) * 8;               //    8 h's per thread

    const float* Aptr = x + (r0 + la_row) * D + la_kh;
    const float* Bptr = WT + (size_t)lb_k * 128 + lb_h;

    u64 acc[8][4];
    #pragma unroll
    for (int i = 0; i < 8; ++i)
        #pragma unroll
        for (int jp = 0; jp < 4; ++jp) acc[i][jp] = 0ULL;

    // ---- prologue: tile 0 into smem ----
    {
        float4 a0 = *(const float4*)(Aptr);
        float4 a1 = *(const float4*)(Aptr + 4);
        float4 b0 = *(const float4*)(Bptr);
        float4 b1 = *(const float4*)(Bptr + 4);
        As[la_kh + 0][la_row] = a0.x; As[la_kh + 1][la_row] = a0.y;
        As[la_kh + 2][la_row] = a0.z; As[la_kh + 3][la_row] = a0.w;
        As[la_kh + 4][la_row] = a1.x; As[la_kh + 5][la_row] = a1.y;
        As[la_kh + 6][la_row] = a1.z; As[la_kh + 7][la_row] = a1.w;
        *(float4*)&Bs[lb_k][lb_h]     = b0;
        *(float4*)&Bs[lb_k][lb_h + 4] = b1;
    }
    __syncthreads();

    const int KS = D / 16;
    float4 pa0, pa1, pb0, pb1;
    for (int ks = 0; ks < KS; ++ks) {
        if (ks + 1 < KS) {                           // prefetch next tile to regs
            Aptr += 16;
            Bptr += 16 * 128;
            pa0 = *(const float4*)(Aptr);
            pa1 = *(const float4*)(Aptr + 4);
            pb0 = *(const float4*)(Bptr);
            pb1 = *(const float4*)(Bptr + 4);
        }
        #pragma unroll
        for (int k = 0; k < 16; ++k) {
            float4 af0 = *(const float4*)&As[k][tm * 8];
            float4 af1 = *(const float4*)&As[k][tm * 8 + 4];
            ulonglong2 bq0 = *(const ulonglong2*)&Bs[k][tn * 8];
            ulonglong2 bq1 = *(const ulonglong2*)&Bs[k][tn * 8 + 4];
            u64 b2[4] = { bq0.x, bq0.y, bq1.x, bq1.y };
            float a[8] = { af0.x, af0.y, af0.z, af0.w,
                           af1.x, af1.y, af1.z, af1.w };
            #pragma unroll
            for (int i = 0; i < 8; ++i) {
                u64 ad = packf2(a[i], a[i]);
                #pragma unroll
                for (int jp = 0; jp < 4; ++jp) ffma2(acc[i][jp], ad, b2[jp]);
            }
        }
        __syncthreads();
        if (ks + 1 < KS) {
            As[la_kh + 0][la_row] = pa0.x; As[la_kh + 1][la_row] = pa0.y;
            As[la_kh + 2][la_row] = pa0.z; As[la_kh + 3][la_row] = pa0.w;
            As[la_kh + 4][la_row] = pa1.x; As[la_kh + 5][la_row] = pa1.y;
            As[la_kh + 6][la_row] = pa1.z; As[la_kh + 7][la_row] = pa1.w;
            *(float4*)&Bs[lb_k][lb_h]     = pb0;
            *(float4*)&Bs[lb_k][lb_h + 4] = pb1;
            __syncthreads();
        }
    }

    // ---- fused score epilogue ----
    #pragma unroll
    for (int i = 0; i < 8; ++i) {
        float p = 0.0f;
        #pragma unroll
        for (int jp = 0; jp < 4; ++jp) {
            float c0, c1;
            unpackf2(acc[i][jp], c0, c1);
            int h0 = tn * 8 + 2 * jp;
            p += sq[h0]     * tanh_fast(c0 + sbu[h0]);
            p += sq[h0 + 1] * tanh_fast(c1 + sbu[h0 + 1]);
        }
        sred[tm * 8 + i][tn] = p;
    }
    __syncthreads();
    if (tid < 128) {
        float s = 0.0f;
        #pragma unroll
        for (int t16 = 0; t16 < 16; ++t16) s += sred[tid][t16];
        sraw[r0 + tid] = s;
    }
}

// ---------------------------------------------------------------------------
// Masked softmax + weighted sum. One CTA (128 threads) per batch row.
// Softmax logic proven in round 3 (rel_err 5.3e-7).
// ---------------------------------------------------------------------------
template <int D>
__global__ void __launch_bounds__(128)
softmax_out_kernel(const float* __restrict__ x,
                   const float* __restrict__ sraw,
                   const unsigned char* __restrict__ mask,
                   float* __restrict__ out) {
    __shared__ float attn[NN];
    const int t = threadIdx.x;
    const int b = blockIdx.x;

    if (t < 32) {
        const float* sb = sraw + (size_t)b * NN;
        const unsigned char* mb = mask + (size_t)b * NN;
        bool v0 = (mb[t] != 0);
        float a0 = v0 ? sb[t] : -CUDART_INF_F;
        bool v1 = false;
        float a1 = -CUDART_INF_F;
        if (t + 32 < NN) { v1 = (mb[t + 32] != 0); a1 = v1 ? sb[t + 32] : -CUDART_INF_F; }
        float mx = fmaxf(a0, a1);
        #pragma unroll
        for (int o = 16; o; o >>= 1)
            mx = fmaxf(mx, __shfl_xor_sync(0xffffffffu, mx, o));
        float e0 = v0 ? __expf(a0 - mx) : 0.0f;
        float e1 = v1 ? __expf(a1 - mx) : 0.0f;
        float su = e0 + e1;
        #pragma unroll
        for (int o = 16; o; o >>= 1)
            su += __shfl_xor_sync(0xffffffffu, su, o);
        float inv = 1.0f / su;
        attn[t] = e0 * inv;
        if (t + 32 < NN) attn[t + 32] = e1 * inv;
    }
    __syncthreads();

    const float* xb = x + (size_t)b * NN * D;
    const int NOUT = D / 128;
    float acc[NOUT];
    #pragma unroll
    for (int c = 0; c < NOUT; ++c) acc[c] = 0.0f;
    #pragma unroll 5
    for (int n = 0; n < NN; ++n) {
        float an = attn[n];
        #pragma unroll
        for (int c = 0; c < NOUT; ++c)
            acc[c] = fmaf(an, xb[(size_t)n * D + t + c * 128], acc[c]);
    }
    #pragma unroll
    for (int c = 0; c < NOUT; ++c)
        out[(size_t)b * D + t + c * 128] = acc[c];
}

// ---------------------------------------------------------------------------
// Launch. Inputs (metadata order):
//  0 users (B,N,128)  1 news (B,N,128)  2 sem (B,N,384)
//  3 user_mask (B,N)  4 news_mask (B,N)
//  5-8 W/b/u/q user   9-12 W/b/u/q news   13-16 W/b/u/q sem
// Output: [agg_users (B,128) | agg_news (B,128) | agg_sem (B,384)] f32
// ---------------------------------------------------------------------------
extern "C" void kernel_launch(void* const* d_in, const int* in_sizes, int n_in,
                              void* d_out, int out_size) {
    const float* users = (const float*)d_in[0];
    const float* news  = (const float*)d_in[1];
    const float* sem   = (const float*)d_in[2];
    const void*  mu    = d_in[3];
    const void*  mn    = d_in[4];
    const float* W_user = (const float*)d_in[5];
    const float* b_user = (const float*)d_in[6];
    const float* u_user = (const float*)d_in[7];
    const float* q_user = (const float*)d_in[8];
    const float* W_news = (const float*)d_in[9];
    const float* b_news = (const float*)d_in[10];
    const float* u_news = (const float*)d_in[11];
    const float* q_news = (const float*)d_in[12];
    const float* W_sem  = (const float*)d_in[13];
    const float* b_sem  = (const float*)d_in[14];
    const float* u_sem  = (const float*)d_in[15];
    const float* q_sem  = (const float*)d_in[16];
    float* out = (float*)d_out;

    void* p;
    cudaGetSymbolAddress(&p, g_mask_user); unsigned char* gmu = (unsigned char*)p;
    cudaGetSymbolAddress(&p, g_mask_news); unsigned char* gmn = (unsigned char*)p;
    cudaGetSymbolAddress(&p, g_WT_u); float* wtu = (float*)p;
    cudaGetSymbolAddress(&p, g_WT_n); float* wtn = (float*)p;
    cudaGetSymbolAddress(&p, g_WT_s); float* wts = (float*)p;
    cudaGetSymbolAddress(&p, g_S_u);  float* su = (float*)p;
    cudaGetSymbolAddress(&p, g_S_n);  float* sn = (float*)p;
    cudaGetSymbolAddress(&p, g_S_s);  float* ss = (float*)p;

    const int NBLK = ROWS / 128;   // 6400 GEMM CTAs

    prep_wt_kernel<<<(81920 + 255) / 256, 256>>>(W_user, W_news, W_sem);       // 1
    detect_mask_kernel<<<1, 256>>>((const unsigned int*)mu);                   // 2
    expand_mask_kernel<<<(ROWS + 255) / 256, 256>>>(mu, gmu, ROWS);            // 3
    expand_mask_kernel<<<(ROWS + 255) / 256, 256>>>(mn, gmn, ROWS);            // 4

    gemm_score_kernel<128><<<NBLK, 256>>>(users, wtu, b_user, u_user, q_user, su); // 5
    gemm_score_kernel<128><<<NBLK, 256>>>(news,  wtn, b_news, u_news, q_news, sn); // 6 (ncu)
    gemm_score_kernel<384><<<NBLK, 256>>>(sem,   wts, b_sem,  u_sem,  q_sem,  ss); // 7

    softmax_out_kernel<128><<<BATCH, 128>>>(users, su, gmu, out);                  // 8
    softmax_out_kernel<128><<<BATCH, 128>>>(news,  sn, gmn, out + (size_t)BATCH * 128); // 9
    softmax_out_kernel<384><<<BATCH, 128>>>(sem,   ss, gmn, out + (size_t)BATCH * 256); // 10
}